// round 8
// baseline (speedup 1.0000x reference)
#include <cuda_runtime.h>
#include <cuda_bf16.h>
#include <math.h>
#include <stdint.h>

#define D_      1024
#define S_      8192
#define B_      4
#define NROWS   (B_ * S_)      // 32768
#define E3      (3 * D_)       // 3072

// ---------------- scratch (static __device__: allocation-free) ----------------
__device__ __nv_bfloat16 g_Xn  [(size_t)NROWS * D_];   // 64 MiB
__device__ __nv_bfloat16 g_Win [(size_t)E3 * D_];      // 6 MiB
__device__ __nv_bfloat16 g_Wpr [(size_t)B_ * D_ * D_]; // 8 MiB  (A-scaled W_out, per batch)
__device__ __nv_bfloat16 g_Qb  [(size_t)NROWS * D_];   // 64 MiB
__device__ __nv_bfloat16 g_Kb  [(size_t)NROWS * D_];   // 64 MiB
__device__ float         g_V   [(size_t)NROWS * D_];   // 128 MiB
__device__ float         g_npQ [(size_t)NROWS * 16];   // 2 MiB  (per-row sq-norm partials)
__device__ float         g_npK [(size_t)NROWS * 16];   // 2 MiB
__device__ float         g_Apart[(size_t)4096 * D_];   // 16 MiB (per-warp partials)
__device__ float         g_A8  [8 * B_ * D_];
__device__ __nv_bfloat16 g_Y   [(size_t)NROWS * D_];   // 64 MiB (Qhat, bf16)

__device__ __forceinline__ uint32_t smem_u32(const void* p) {
    uint32_t a;
    asm("{ .reg .u64 t; cvta.to.shared.u64 t, %1; cvt.u32.u64 %0, t; }" : "=r"(a) : "l"(p));
    return a;
}

// ---------------- fp32 -> bf16 weight conversion (W_in) ----------------
__global__ void k_convert(const float* __restrict__ src, int n)
{
    int i = (blockIdx.x * blockDim.x + threadIdx.x) * 4;
    if (i >= n) return;
    float4 v = *(const float4*)(src + i);
    *(__nv_bfloat162*)(g_Win + i)     = __floats2bfloat162_rn(v.x, v.y);
    *(__nv_bfloat162*)(g_Win + i + 2) = __floats2bfloat162_rn(v.z, v.w);
}

// ---------------- LayerNorm: warp-per-row, no barriers ----------------
__global__ void __launch_bounds__(256) k_layernorm(
    const float* __restrict__ X, const float* __restrict__ lg, const float* __restrict__ lb)
{
    const int w    = threadIdx.x >> 5;
    const int lane = threadIdx.x & 31;
    const int row  = blockIdx.x * 8 + w;
    const int c0   = 4 * lane;
    const float* xp = X + (size_t)row * D_ + c0;

    float x[8][4];
    float s = 0.f, sq = 0.f;
    #pragma unroll
    for (int k = 0; k < 8; k++) {
        float4 v = *(const float4*)(xp + 128 * k);
        x[k][0] = v.x; x[k][1] = v.y; x[k][2] = v.z; x[k][3] = v.w;
        s  += v.x + v.y + v.z + v.w;
        sq += v.x * v.x + v.y * v.y + v.z * v.z + v.w * v.w;
    }
    #pragma unroll
    for (int o = 16; o; o >>= 1) {
        s  += __shfl_xor_sync(0xffffffffu, s, o);
        sq += __shfl_xor_sync(0xffffffffu, sq, o);
    }
    const float mu  = s * (1.f / D_);
    const float var = sq * (1.f / D_) - mu * mu;
    const float rs  = rsqrtf(var + 1e-5f);

    __nv_bfloat16* op = g_Xn + (size_t)row * D_ + c0;
    #pragma unroll
    for (int k = 0; k < 8; k++) {
        float4 g4 = *(const float4*)(lg + c0 + 128 * k);
        float4 b4 = *(const float4*)(lb + c0 + 128 * k);
        float y0 = (x[k][0] - mu) * rs * g4.x + b4.x;
        float y1 = (x[k][1] - mu) * rs * g4.y + b4.y;
        float y2 = (x[k][2] - mu) * rs * g4.z + b4.z;
        float y3 = (x[k][3] - mu) * rs * g4.w + b4.w;
        *(__nv_bfloat162*)(op + 128 * k)     = __floats2bfloat162_rn(y0, y1);
        *(__nv_bfloat162*)(op + 128 * k + 2) = __floats2bfloat162_rn(y2, y3);
    }
}

// ---------------- mma.sync bf16 GEMM ----------------
// 128x256 block tile, 8 warps (2m x 4n), warp tile 64x64, KC=64, 4-stage cp.async.
// mode 0: A=g_Xn, B=g_Win; C -> g_Qb/g_Kb (bf16, + norm partials) or g_V (fp32)
// mode 1: A=g_Y,  B=g_Wpr[batch]; C -> out (fp32, += X)
#define KC 64
#define NCHUNK 16
#define ASTAGE 16384
#define BSTAGE 32768
#define STAGE_BYTES (ASTAGE + BSTAGE)     // 48 KB
#define GEMM_SMEM (4 * STAGE_BYTES)       // 192 KB

__global__ void __launch_bounds__(256, 1) k_gemm(
    const float* __restrict__ addX, float* __restrict__ Cout, int mode)
{
    extern __shared__ char smem[];
    const int K = 1024;
    const int tid  = threadIdx.x;
    const int w    = tid >> 5;
    const int lane = tid & 31;
    const int wm   = w & 1;
    const int wn   = w >> 1;
    const int m0 = blockIdx.y * 128;
    const int n0 = blockIdx.x * 256;

    const __nv_bfloat16* Ag = mode ? g_Y : g_Xn;
    const __nv_bfloat16* Bg = mode ? (g_Wpr + (size_t)(m0 >> 13) * D_ * D_) : g_Win;

    const uint32_t sbase = smem_u32(smem);

    auto issue = [&](int kt) {
        const uint32_t st = sbase + (kt & 3) * STAGE_BYTES;
        #pragma unroll
        for (int i = 0; i < 12; i++) {
            int vec = i * 256 + tid;
            int isB = vec >= 1024;
            int vv  = isB ? vec - 1024 : vec;
            int row = vv >> 3;
            int c   = vv & 7;
            const __nv_bfloat16* src =
                (isB ? Bg + (size_t)(n0 + row) * K : Ag + (size_t)(m0 + row) * K)
                + kt * KC + c * 8;
            uint32_t dst = st + (isB ? ASTAGE : 0) + row * 128 + (((c ^ (row & 7)) << 4));
            asm volatile("cp.async.cg.shared.global [%0], [%1], 16;" :: "r"(dst), "l"(src));
        }
        asm volatile("cp.async.commit_group;" ::: "memory");
    };

    float acc[4][8][4];
    #pragma unroll
    for (int mi = 0; mi < 4; mi++)
        #pragma unroll
        for (int ni = 0; ni < 8; ni++)
            #pragma unroll
            for (int e = 0; e < 4; e++) acc[mi][ni][e] = 0.f;

    issue(0); issue(1); issue(2);

    const int lr = lane & 15;
    const int lc = lane >> 4;

    uint32_t a[2][4][4], b[2][8][2];

    for (int kt = 0; kt < NCHUNK; kt++) {
        asm volatile("cp.async.wait_group 2;" ::: "memory");
        __syncthreads();
        if (kt + 3 < NCHUNK) issue(kt + 3);
        else asm volatile("cp.async.commit_group;" ::: "memory");

        const uint32_t sA = sbase + (kt & 3) * STAGE_BYTES;
        const uint32_t sB = sA + ASTAGE;

        {
            const int c = lc;
            #pragma unroll
            for (int mi = 0; mi < 4; mi++) {
                int r = wm * 64 + mi * 16 + lr;
                uint32_t addr = sA + r * 128 + ((c ^ (r & 7)) << 4);
                asm volatile("ldmatrix.sync.aligned.m8n8.x4.shared.b16 {%0,%1,%2,%3}, [%4];"
                    : "=r"(a[0][mi][0]), "=r"(a[0][mi][1]), "=r"(a[0][mi][2]), "=r"(a[0][mi][3])
                    : "r"(addr));
            }
            #pragma unroll
            for (int nb = 0; nb < 4; nb++) {
                int r = wn * 64 + nb * 16 + lr;
                uint32_t addr = sB + r * 128 + ((c ^ (r & 7)) << 4);
                uint32_t t0, t1, t2, t3;
                asm volatile("ldmatrix.sync.aligned.m8n8.x4.shared.b16 {%0,%1,%2,%3}, [%4];"
                    : "=r"(t0), "=r"(t1), "=r"(t2), "=r"(t3) : "r"(addr));
                b[0][nb * 2][0] = t0; b[0][nb * 2][1] = t2;
                b[0][nb * 2 + 1][0] = t1; b[0][nb * 2 + 1][1] = t3;
            }
        }

        #pragma unroll
        for (int ks = 0; ks < 4; ks++) {
            const int cur = ks & 1;
            const int nxt = cur ^ 1;
            if (ks < 3) {
                const int c = (ks + 1) * 2 + lc;
                #pragma unroll
                for (int mi = 0; mi < 4; mi++) {
                    int r = wm * 64 + mi * 16 + lr;
                    uint32_t addr = sA + r * 128 + ((c ^ (r & 7)) << 4);
                    asm volatile("ldmatrix.sync.aligned.m8n8.x4.shared.b16 {%0,%1,%2,%3}, [%4];"
                        : "=r"(a[nxt][mi][0]), "=r"(a[nxt][mi][1]),
                          "=r"(a[nxt][mi][2]), "=r"(a[nxt][mi][3]) : "r"(addr));
                }
                #pragma unroll
                for (int nb = 0; nb < 4; nb++) {
                    int r = wn * 64 + nb * 16 + lr;
                    uint32_t addr = sB + r * 128 + ((c ^ (r & 7)) << 4);
                    uint32_t t0, t1, t2, t3;
                    asm volatile("ldmatrix.sync.aligned.m8n8.x4.shared.b16 {%0,%1,%2,%3}, [%4];"
                        : "=r"(t0), "=r"(t1), "=r"(t2), "=r"(t3) : "r"(addr));
                    b[nxt][nb * 2][0] = t0; b[nxt][nb * 2][1] = t2;
                    b[nxt][nb * 2 + 1][0] = t1; b[nxt][nb * 2 + 1][1] = t3;
                }
            }
            #pragma unroll
            for (int mi = 0; mi < 4; mi++)
                #pragma unroll
                for (int ni = 0; ni < 8; ni++) {
                    asm volatile(
                        "mma.sync.aligned.m16n8k16.row.col.f32.bf16.bf16.f32 "
                        "{%0,%1,%2,%3}, {%4,%5,%6,%7}, {%8,%9}, {%0,%1,%2,%3};"
                        : "+f"(acc[mi][ni][0]), "+f"(acc[mi][ni][1]),
                          "+f"(acc[mi][ni][2]), "+f"(acc[mi][ni][3])
                        : "r"(a[cur][mi][0]), "r"(a[cur][mi][1]),
                          "r"(a[cur][mi][2]), "r"(a[cur][mi][3]),
                          "r"(b[cur][ni][0]), "r"(b[cur][ni][1]));
                }
        }
    }

    const int rbase = m0 + wm * 64 + (lane >> 2);
    if (mode) {
        const int cbase = n0 + wn * 64 + (lane & 3) * 2;
        #pragma unroll
        for (int mi = 0; mi < 4; mi++)
            #pragma unroll
            for (int ni = 0; ni < 8; ni++) {
                int rr = rbase + mi * 16;
                int cc = cbase + ni * 8;
                size_t i0 = (size_t)rr * D_ + cc;
                size_t i1 = (size_t)(rr + 8) * D_ + cc;
                float2 x0 = *(const float2*)(addX + i0);
                float2 x1 = *(const float2*)(addX + i1);
                *(float2*)(Cout + i0) = make_float2(acc[mi][ni][0] + x0.x, acc[mi][ni][1] + x0.y);
                *(float2*)(Cout + i1) = make_float2(acc[mi][ni][2] + x1.x, acc[mi][ni][3] + x1.y);
            }
    } else {
        const int region = n0 >> 10;           // 0=Q, 1=K, 2=V
        const int cbase  = (n0 & 1023) + wn * 64 + (lane & 3) * 2;
        if (region < 2) {
            __nv_bfloat16* Cb = region ? g_Kb : g_Qb;
            float* np = region ? g_npK : g_npQ;
            const int widx = ((n0 >> 8) & 3) * 4 + wn;     // 0..15 stripe index
            #pragma unroll
            for (int mi = 0; mi < 4; mi++) {
                float s0 = 0.f, s1 = 0.f;
                #pragma unroll
                for (int ni = 0; ni < 8; ni++) {
                    int rr = rbase + mi * 16;
                    int cc = cbase + ni * 8;
                    *(__nv_bfloat162*)(Cb + (size_t)rr * D_ + cc) =
                        __floats2bfloat162_rn(acc[mi][ni][0], acc[mi][ni][1]);
                    *(__nv_bfloat162*)(Cb + (size_t)(rr + 8) * D_ + cc) =
                        __floats2bfloat162_rn(acc[mi][ni][2], acc[mi][ni][3]);
                    s0 += acc[mi][ni][0] * acc[mi][ni][0] + acc[mi][ni][1] * acc[mi][ni][1];
                    s1 += acc[mi][ni][2] * acc[mi][ni][2] + acc[mi][ni][3] * acc[mi][ni][3];
                }
                s0 += __shfl_xor_sync(0xffffffffu, s0, 1);
                s0 += __shfl_xor_sync(0xffffffffu, s0, 2);
                s1 += __shfl_xor_sync(0xffffffffu, s1, 1);
                s1 += __shfl_xor_sync(0xffffffffu, s1, 2);
                if ((lane & 3) == 0) {
                    int rr = rbase + mi * 16;
                    np[(size_t)rr * 16 + widx]       = s0;
                    np[(size_t)(rr + 8) * 16 + widx] = s1;
                }
            }
        } else {
            #pragma unroll
            for (int mi = 0; mi < 4; mi++)
                #pragma unroll
                for (int ni = 0; ni < 8; ni++) {
                    int rr = rbase + mi * 16;
                    int cc = cbase + ni * 8;
                    *(float2*)(g_V + (size_t)rr * D_ + cc) =
                        make_float2(acc[mi][ni][0], acc[mi][ni][1]);
                    *(float2*)(g_V + (size_t)(rr + 8) * D_ + cc) =
                        make_float2(acc[mi][ni][2], acc[mi][ni][3]);
                }
        }
    }
}

// ---------------- rotary + scale + A partials : single pass, no reductions ----------------
// Norms read from precomputed partials (fixed order -> deterministic).
// Block 256 (8 warps); each warp owns 8 rows. Grid = NROWS/64.
__global__ void __launch_bounds__(256) k_rowproc()
{
    const int w     = threadIdx.x >> 5;
    const int lane  = threadIdx.x & 31;
    const int gwarp = blockIdx.x * 8 + w;     // 0..4095
    const int row0  = gwarp * 8;

    float invf0[4], invf1[4];
    {
        double b0 = pow(10000.0, -(double)(2 * lane) * (1.0 / 256.0));
        double b1 = pow(10000.0, -(double)(2 * lane + 1) * (1.0 / 256.0));
        double f = 1.0;
        #pragma unroll
        for (int k = 0; k < 4; k++) {
            invf0[k] = (float)(b0 * f);
            invf1[k] = (float)(b1 * f);
            f *= 0.1;
        }
    }

    float accA[8][4];
    #pragma unroll
    for (int k = 0; k < 8; k++)
        #pragma unroll
        for (int e = 0; e < 4; e++) accA[k][e] = 0.f;

    const int c0 = 4 * lane;

    for (int r8 = 0; r8 < 8; r8++) {
        const int row = row0 + r8;
        const float s = (float)(row & 8191);
        const size_t base = (size_t)row * D_ + c0;

        // norms from partials (broadcast loads, fixed order)
        float qs = 0.f, ks = 0.f;
        {
            const float4* npq = (const float4*)(g_npQ + (size_t)row * 16);
            const float4* npk = (const float4*)(g_npK + (size_t)row * 16);
            #pragma unroll
            for (int i = 0; i < 4; i++) {
                float4 tq = npq[i];
                float4 tk = npk[i];
                qs += tq.x + tq.y + tq.z + tq.w;
                ks += tk.x + tk.y + tk.z + tk.w;
            }
        }
        const float qi = rsqrtf(qs + 1e-6f);
        const float ki = rsqrtf(ks + 1e-6f);

        #pragma unroll
        for (int k = 0; k < 8; k++) {
            const __nv_bfloat162* qp = (const __nv_bfloat162*)(g_Qb + base + 128 * k);
            const __nv_bfloat162* kp = (const __nv_bfloat162*)(g_Kb + base + 128 * k);
            float2 qa = __bfloat1622float2(qp[0]);
            float2 qb = __bfloat1622float2(qp[1]);
            float2 ka = __bfloat1622float2(kp[0]);
            float2 kb = __bfloat1622float2(kp[1]);
            if (k < 4) {
                float sn0, cs0, sn1, cs1;
                sincosf(s * invf0[k], &sn0, &cs0);
                sincosf(s * invf1[k], &sn1, &cs1);
                float a, bb;
                a = qa.x * cs0 - qa.y * sn0; bb = qa.y * cs0 + qa.x * sn0; qa.x = a; qa.y = bb;
                a = qb.x * cs1 - qb.y * sn1; bb = qb.y * cs1 + qb.x * sn1; qb.x = a; qb.y = bb;
                a = ka.x * cs0 - ka.y * sn0; bb = ka.y * cs0 + ka.x * sn0; ka.x = a; ka.y = bb;
                a = kb.x * cs1 - kb.y * sn1; bb = kb.y * cs1 + kb.x * sn1; kb.x = a; kb.y = bb;
            }
            float4 v = *(const float4*)(g_V + base + 128 * k);
            accA[k][0] += ka.x * ki * v.x;
            accA[k][1] += ka.y * ki * v.y;
            accA[k][2] += kb.x * ki * v.z;
            accA[k][3] += kb.y * ki * v.w;
            __nv_bfloat16* yp = g_Y + base + 128 * k;
            *(__nv_bfloat162*)(yp)     = __floats2bfloat162_rn(qa.x * qi, qa.y * qi);
            *(__nv_bfloat162*)(yp + 2) = __floats2bfloat162_rn(qb.x * qi, qb.y * qi);
        }
    }

    const size_t ap = (size_t)gwarp * D_ + c0;
    #pragma unroll
    for (int k = 0; k < 8; k++)
        *(float4*)&g_Apart[ap + 128 * k] =
            make_float4(accA[k][0], accA[k][1], accA[k][2], accA[k][3]);
}

// ---------------- reduce A partials (stage 1: 4096 groups -> 8x per (b,d)) ----------------
__global__ void k_reduceA()
{
    int idx = blockIdx.x * blockDim.x + threadIdx.x;   // 0..32767
    int sub = idx >> 12;       // 0..7
    int rem = idx & 4095;      // b*1024 + d
    int b   = rem >> 10;
    int d   = rem & 1023;
    int g0  = b * 1024 + sub * 128;
    const float* p = g_Apart + (size_t)g0 * D_ + d;
    float s = 0.f;
    #pragma unroll 8
    for (int g = 0; g < 128; g++) s += p[(size_t)g * D_];
    g_A8[sub * 4096 + rem] = s;
}

// ---------------- W'_b = A_b (*) W_out  -> bf16, 4 copies (folds stage-2 reduce) ------------
__global__ void __launch_bounds__(256) k_scaleW(const float* __restrict__ Wout)
{
    int i4 = (blockIdx.x * blockDim.x + threadIdx.x) * 4;   // over D_*D_
    if (i4 >= D_ * D_) return;
    int d = i4 & 1023;
    float4 w = *(const float4*)(Wout + i4);
    #pragma unroll
    for (int b = 0; b < B_; b++) {
        float4 a = make_float4(0.f, 0.f, 0.f, 0.f);
        #pragma unroll
        for (int sub = 0; sub < 8; sub++) {
            float4 t = *(const float4*)(g_A8 + sub * 4096 + b * 1024 + d);
            a.x += t.x; a.y += t.y; a.z += t.z; a.w += t.w;
        }
        __nv_bfloat16* dst = g_Wpr + (size_t)b * D_ * D_ + i4;
        *(__nv_bfloat162*)(dst)     = __floats2bfloat162_rn(w.x * a.x, w.y * a.y);
        *(__nv_bfloat162*)(dst + 2) = __floats2bfloat162_rn(w.z * a.z, w.w * a.w);
    }
}

// ---------------- launch ----------------
extern "C" void kernel_launch(void* const* d_in, const int* in_sizes, int n_in,
                              void* d_out, int out_size)
{
    const float* X    = (const float*)d_in[0];
    const float* Win  = (const float*)d_in[1];
    const float* Wout = (const float*)d_in[2];
    const float* lg   = (const float*)d_in[3];
    const float* lb   = (const float*)d_in[4];
    float* out = (float*)d_out;

    cudaFuncSetAttribute(k_gemm, cudaFuncAttributeMaxDynamicSharedMemorySize, GEMM_SMEM);

    k_convert<<<(E3 * D_) / 4 / 256, 256>>>(Win, E3 * D_);
    k_layernorm<<<NROWS / 8, 256>>>(X, lg, lb);
    k_gemm<<<dim3(E3 / 256, NROWS / 128), 256, GEMM_SMEM>>>(nullptr, nullptr, 0);
    k_rowproc<<<NROWS / 64, 256>>>();
    k_reduceA<<<128, 256>>>();
    k_scaleW<<<D_ * D_ / 4 / 256, 256>>>(Wout);
    k_gemm<<<dim3(D_ / 256, NROWS / 128), 256, GEMM_SMEM>>>(X, out, 1);
}